// round 1
// baseline (speedup 1.0000x reference)
#include <cuda_runtime.h>
#include <math.h>

// ---------------------------------------------------------------------------
// FocalLoss (RetinaNet-style) on GB300.
// Inputs (metadata order):
//   d_in[0] classifications float32 [B, A, C]
//   d_in[1] regressions     float32 [B, A, 4]
//   d_in[2] anchors         float32 [1, A, 4]   (y1, x1, y2, x2)
//   d_in[3] annotations     float32 [B, M, 5]   (x1, y1, x2, y2, label)
// Output: float32 [2] = (clf_loss_weighted, reg_loss_weighted)
// ---------------------------------------------------------------------------

#define FL_EPS    1e-4f
#define FL_ACCEPT 0.5f
#define FL_REJECT 0.4f
#define MAX_B     16
#define MAX_M     128

__device__ double g_clf_sum[MAX_B];
__device__ double g_sl1_sum[MAX_B];
__device__ int    g_nm[MAX_B];

__global__ void fl_init_kernel() {
    int i = threadIdx.x;
    if (i < MAX_B) {
        g_clf_sum[i] = 0.0;
        g_sl1_sum[i] = 0.0;
        g_nm[i]      = 0;
    }
}

__global__ void fl_main_kernel(const float* __restrict__ clf,
                               const float* __restrict__ reg,
                               const float* __restrict__ anc,
                               const float* __restrict__ ann,
                               int A, int C, int M) {
    const int b      = blockIdx.y;
    const int warpId = threadIdx.x >> 5;
    const int lane   = threadIdx.x & 31;
    const int nWarps = blockDim.x >> 5;
    const int a      = blockIdx.x * nWarps + warpId;

    __shared__ float  s_ann[MAX_M * 5];
    __shared__ double s_clf, s_sl1;
    __shared__ int    s_nm;

    if (threadIdx.x == 0) { s_clf = 0.0; s_sl1 = 0.0; s_nm = 0; }
    const int annN = M * 5;
    for (int i = threadIdx.x; i < annN; i += blockDim.x)
        s_ann[i] = ann[(size_t)b * annN + i];
    __syncthreads();

    float warp_clf = 0.0f;
    float warp_sl1 = 0.0f;
    int   warp_nm  = 0;

    if (a < A) {
        // Anchor box (y1, x1, y2, x2)
        const float ay1 = anc[a * 4 + 0];
        const float ax1 = anc[a * 4 + 1];
        const float ay2 = anc[a * 4 + 2];
        const float ax2 = anc[a * 4 + 3];
        const float aarea = (ax2 - ax1) * (ay2 - ay1);

        // ---- IoU vs all M boxes; argmax with first-index tiebreak --------
        float v   = -2.0f;   // strictly below the -1.0 "invalid" sentinel
        int   idx = 0;
        for (int j = lane; j < M; j += 32) {
            const float bx1 = s_ann[j * 5 + 0];
            const float by1 = s_ann[j * 5 + 1];
            const float bx2 = s_ann[j * 5 + 2];
            const float by2 = s_ann[j * 5 + 3];
            const float lbl = s_ann[j * 5 + 4];
            float iw = fminf(ax2, bx2) - fmaxf(ax1, bx1); iw = fmaxf(iw, 0.0f);
            float ih = fminf(ay2, by2) - fmaxf(ay1, by1); ih = fmaxf(ih, 0.0f);
            const float inter = iw * ih;
            const float uni = fmaxf(aarea + (bx2 - bx1) * (by2 - by1) - inter, 1e-8f);
            float iou = inter / uni;
            if (lbl == -1.0f) iou = -1.0f;
            if (iou > v) { v = iou; idx = j; }   // strict >: keeps lowest index
        }
        #pragma unroll
        for (int off = 16; off; off >>= 1) {
            const float v2 = __shfl_xor_sync(0xffffffffu, v, off);
            const int   i2 = __shfl_xor_sync(0xffffffffu, idx, off);
            if (v2 > v || (v2 == v && i2 < idx)) { v = v2; idx = i2; }
        }

        const bool matched   = v > FL_ACCEPT;
        const bool unmatched = v < FL_REJECT;
        const int  gt        = (int)s_ann[idx * 5 + 4] - 1;

        // ---- classification focal loss (skip dead-zone anchors) ----------
        if (matched || unmatched) {
            const float* crow = clf + ((size_t)b * A + a) * C;
            float lsum = 0.0f;
            for (int c = lane; c < C; c += 32) {
                float p = crow[c];
                p = fminf(fmaxf(p, FL_EPS), 1.0f - FL_EPS);
                const bool ispos = matched && (c == gt);
                // pos = 0.25*(1-p)^2*(-log p); neg = 0.75*p^2*(-log(1-p))
                // unified: q = ispos ? p : 1-p; w = ispos ? 0.25 : 0.75
                const float q  = ispos ? p : (1.0f - p);
                const float w  = ispos ? 0.25f : 0.75f;
                const float om = 1.0f - q;
                lsum += w * om * om * (-__logf(q));
            }
            #pragma unroll
            for (int off = 16; off; off >>= 1)
                lsum += __shfl_xor_sync(0xffffffffu, lsum, off);
            warp_clf = lsum;
        }

        // ---- regression smooth-L1 (matched anchors only) -----------------
        if (matched) {
            warp_nm = 1;
            if (lane == 0) {
                const float gx1 = s_ann[idx * 5 + 0];
                const float gy1 = s_ann[idx * 5 + 1];
                const float gx2 = s_ann[idx * 5 + 2];
                const float gy2 = s_ann[idx * 5 + 3];
                const float gwr = gx2 - gx1;
                const float ghr = gy2 - gy1;
                const float gcx = gx1 + 0.5f * gwr;
                const float gcy = gy1 + 0.5f * ghr;
                const float gw  = fmaxf(gwr, 1.0f);
                const float gh  = fmaxf(ghr, 1.0f);
                const float aw  = ax2 - ax1;
                const float ah  = ay2 - ay1;
                const float acx = ax1 + 0.5f * aw;
                const float acy = ay1 + 0.5f * ah;
                float tt[4];
                tt[0] = (gcy - acy) / ah;
                tt[1] = (gcx - acx) / aw;
                tt[2] = __logf(gh / ah);
                tt[3] = __logf(gw / aw);
                const float* rrow = reg + ((size_t)b * A + a) * 4;
                float s = 0.0f;
                #pragma unroll
                for (int k = 0; k < 4; k++) {
                    const float d = fabsf(9.0f * (rrow[k] - tt[k]));
                    s += (d < 1.0f) ? 0.5f * d * d : (d - 0.5f);
                }
                warp_sl1 = s;
            }
        }
    }

    // ---- block-level reduction, then 3 global atomics per block ----------
    if (lane == 0) {
        if (warp_clf != 0.0f) atomicAdd(&s_clf, (double)warp_clf);
        if (warp_sl1 != 0.0f) atomicAdd(&s_sl1, (double)warp_sl1);
        if (warp_nm)          atomicAdd(&s_nm, 1);
    }
    __syncthreads();
    if (threadIdx.x == 0) {
        if (s_clf != 0.0) atomicAdd(&g_clf_sum[b], s_clf);
        if (s_sl1 != 0.0) atomicAdd(&g_sl1_sum[b], s_sl1);
        if (s_nm)         atomicAdd(&g_nm[b], s_nm);
    }
}

__global__ void fl_fin_kernel(float* __restrict__ out, int B) {
    if (threadIdx.x == 0 && blockIdx.x == 0) {
        double cl = 0.0, rl = 0.0;
        for (int b = 0; b < B; b++) {
            const int nm = g_nm[b];
            const int dn = nm > 1 ? nm : 1;
            cl += g_clf_sum[b] / (double)dn;
            if (nm > 0) rl += g_sl1_sum[b] / (double)(4 * nm);
        }
        out[0] = (float)(cl / (double)B);          // CLF_W = 1.0
        out[1] = (float)(50.0 * rl / (double)B);   // REG_W = 50.0
    }
}

extern "C" void kernel_launch(void* const* d_in, const int* in_sizes, int n_in,
                              void* d_out, int out_size) {
    const float* clf = (const float*)d_in[0];
    const float* reg = (const float*)d_in[1];
    const float* anc = (const float*)d_in[2];
    const float* ann = (const float*)d_in[3];
    float* out = (float*)d_out;

    const int A = in_sizes[2] / 4;                       // anchors: 1*A*4
    const int B = in_sizes[1] / (4 * A);                 // regressions: B*A*4
    const int C = (int)((long long)in_sizes[0] / ((long long)B * A)); // B*A*C
    const int M = in_sizes[3] / (5 * B);                 // annotations: B*M*5

    fl_init_kernel<<<1, 32>>>();

    const int threads = 256;
    const int warpsPerBlock = threads / 32;
    dim3 grid((A + warpsPerBlock - 1) / warpsPerBlock, B);
    fl_main_kernel<<<grid, threads>>>(clf, reg, anc, ann, A, C, M);

    fl_fin_kernel<<<1, 32>>>(out, B);
}

// round 2
// speedup vs baseline: 2.1503x; 2.1503x over previous
#include <cuda_runtime.h>
#include <math.h>

// ---------------------------------------------------------------------------
// FocalLoss (RetinaNet-style) on GB300 — two-phase decoupled design.
//   Phase A: per-anchor matching (thread per anchor) -> meta codes + reg loss
//   Phase B: branch-free float4 stream over classifications -> clf loss
// Inputs (metadata order):
//   d_in[0] classifications float32 [B, A, C]
//   d_in[1] regressions     float32 [B, A, 4]
//   d_in[2] anchors         float32 [1, A, 4]   (y1, x1, y2, x2)
//   d_in[3] annotations     float32 [B, M, 5]   (x1, y1, x2, y2, label)
// Output: float32 [2] = (clf_loss_weighted, reg_loss_weighted)
// ---------------------------------------------------------------------------

#define FL_EPS    1e-4f
#define FL_ACCEPT 0.5f
#define FL_REJECT 0.4f
#define MAX_B     16
#define MAX_M     128
#define META_CAP  (1 << 20)      // >= B*A (8*49104 = 392832)
#define UNMATCHED_SENTINEL 0x3fffffff

__device__ double g_clf_sum[MAX_B];
__device__ double g_sl1_sum[MAX_B];
__device__ int    g_nm[MAX_B];
__device__ int    g_meta[META_CAP];   // per (b,a): gt class | sentinel | -1(dead)

__global__ void fl_init_kernel() {
    int i = threadIdx.x;
    if (i < MAX_B) {
        g_clf_sum[i] = 0.0;
        g_sl1_sum[i] = 0.0;
        g_nm[i]      = 0;
    }
}

// ---------------- Phase A: matching + regression loss ----------------------
__global__ void fl_match_kernel(const float4* __restrict__ anc,
                                const float4* __restrict__ reg,
                                const float* __restrict__ ann,
                                int A, int M) {
    const int b = blockIdx.y;
    const int a = blockIdx.x * blockDim.x + threadIdx.x;

    __shared__ float  s_ann[MAX_M * 5];
    __shared__ double s_sl1;
    __shared__ int    s_nm;

    if (threadIdx.x == 0) { s_sl1 = 0.0; s_nm = 0; }
    const int annN = M * 5;
    for (int i = threadIdx.x; i < annN; i += blockDim.x)
        s_ann[i] = ann[(size_t)b * annN + i];
    __syncthreads();

    if (a < A) {
        const float4 av = anc[a];            // y1, x1, y2, x2
        const float ay1 = av.x, ax1 = av.y, ay2 = av.z, ax2 = av.w;
        const float aarea = (ax2 - ax1) * (ay2 - ay1);

        // sequential argmax keeps jnp.argmax first-index tiebreak
        float v   = -2.0f;
        int   idx = 0;
        for (int j = 0; j < M; j++) {
            const float bx1 = s_ann[j * 5 + 0];
            const float by1 = s_ann[j * 5 + 1];
            const float bx2 = s_ann[j * 5 + 2];
            const float by2 = s_ann[j * 5 + 3];
            float iw = fminf(ax2, bx2) - fmaxf(ax1, bx1); iw = fmaxf(iw, 0.0f);
            float ih = fminf(ay2, by2) - fmaxf(ay1, by1); ih = fmaxf(ih, 0.0f);
            const float inter = iw * ih;
            const float uni = fmaxf(aarea + (bx2 - bx1) * (by2 - by1) - inter, 1e-8f);
            float iou = inter / uni;
            if (s_ann[j * 5 + 4] == -1.0f) iou = -1.0f;
            if (iou > v) { v = iou; idx = j; }
        }

        const bool matched   = v > FL_ACCEPT;
        const bool unmatched = v < FL_REJECT;

        int meta = -1;                                   // dead zone
        if (unmatched) meta = UNMATCHED_SENTINEL;        // all-negative row
        if (matched)   meta = (int)s_ann[idx * 5 + 4] - 1;
        g_meta[b * A + a] = meta;

        if (matched) {
            const float gx1 = s_ann[idx * 5 + 0];
            const float gy1 = s_ann[idx * 5 + 1];
            const float gx2 = s_ann[idx * 5 + 2];
            const float gy2 = s_ann[idx * 5 + 3];
            const float gwr = gx2 - gx1;
            const float ghr = gy2 - gy1;
            const float gcx = gx1 + 0.5f * gwr;
            const float gcy = gy1 + 0.5f * ghr;
            const float gw  = fmaxf(gwr, 1.0f);
            const float gh  = fmaxf(ghr, 1.0f);
            const float aw  = ax2 - ax1;
            const float ah  = ay2 - ay1;
            const float acx = ax1 + 0.5f * aw;
            const float acy = ay1 + 0.5f * ah;
            const float4 rv = reg[(size_t)b * A + a];
            float s = 0.0f;
            {
                float d;
                d = fabsf(9.0f * (rv.x - (gcy - acy) / ah));
                s += (d < 1.0f) ? 0.5f * d * d : (d - 0.5f);
                d = fabsf(9.0f * (rv.y - (gcx - acx) / aw));
                s += (d < 1.0f) ? 0.5f * d * d : (d - 0.5f);
                d = fabsf(9.0f * (rv.z - __logf(gh / ah)));
                s += (d < 1.0f) ? 0.5f * d * d : (d - 0.5f);
                d = fabsf(9.0f * (rv.w - __logf(gw / aw)));
                s += (d < 1.0f) ? 0.5f * d * d : (d - 0.5f);
            }
            atomicAdd(&s_sl1, (double)s);
            atomicAdd(&s_nm, 1);
        }
    }

    __syncthreads();
    if (threadIdx.x == 0) {
        if (s_sl1 != 0.0) atomicAdd(&g_sl1_sum[b], s_sl1);
        if (s_nm)         atomicAdd(&g_nm[b], s_nm);
    }
}

// ---------------- Phase B: streaming focal loss ----------------------------
__device__ __forceinline__ float fl_elem(float p, int c, int m) {
    p = fminf(fmaxf(p, FL_EPS), 1.0f - FL_EPS);
    const bool dead  = (m < 0);
    const bool ispos = (c == m);
    const float q  = ispos ? p : (1.0f - p);
    const float w  = dead ? 0.0f : (ispos ? 0.25f : 0.75f);
    const float om = 1.0f - q;
    return w * om * om * (-__logf(q));
}

template <int CC>
__global__ void fl_clf_kernel(const float4* __restrict__ clf,
                              int A, int C, int perImgV4) {
    const int b = blockIdx.y;
    const int  Cv = (CC > 0) ? CC : C;
    const float4* base = clf + (size_t)b * perImgV4;
    const int* __restrict__ meta = g_meta + b * A;

    float acc = 0.0f;
    const int stride = gridDim.x * blockDim.x;
    for (int i = blockIdx.x * blockDim.x + threadIdx.x; i < perImgV4; i += stride) {
        const float4 v = base[i];
        const int e0 = i * 4;
        {
            const int e = e0 + 0; const int a = e / Cv; acc += fl_elem(v.x, e - a * Cv, __ldg(&meta[a]));
        }
        {
            const int e = e0 + 1; const int a = e / Cv; acc += fl_elem(v.y, e - a * Cv, __ldg(&meta[a]));
        }
        {
            const int e = e0 + 2; const int a = e / Cv; acc += fl_elem(v.z, e - a * Cv, __ldg(&meta[a]));
        }
        {
            const int e = e0 + 3; const int a = e / Cv; acc += fl_elem(v.w, e - a * Cv, __ldg(&meta[a]));
        }
    }

    // warp reduce -> shared double -> 1 global atomic per block
    #pragma unroll
    for (int off = 16; off; off >>= 1)
        acc += __shfl_xor_sync(0xffffffffu, acc, off);

    __shared__ double s_acc;
    if (threadIdx.x == 0) s_acc = 0.0;
    __syncthreads();
    if ((threadIdx.x & 31) == 0 && acc != 0.0f)
        atomicAdd(&s_acc, (double)acc);
    __syncthreads();
    if (threadIdx.x == 0 && s_acc != 0.0)
        atomicAdd(&g_clf_sum[b], s_acc);
}

__global__ void fl_fin_kernel(float* __restrict__ out, int B) {
    if (threadIdx.x == 0 && blockIdx.x == 0) {
        double cl = 0.0, rl = 0.0;
        for (int b = 0; b < B; b++) {
            const int nm = g_nm[b];
            const int dn = nm > 1 ? nm : 1;
            cl += g_clf_sum[b] / (double)dn;
            if (nm > 0) rl += g_sl1_sum[b] / (double)(4 * nm);
        }
        out[0] = (float)(cl / (double)B);          // CLF_W = 1.0
        out[1] = (float)(50.0 * rl / (double)B);   // REG_W = 50.0
    }
}

extern "C" void kernel_launch(void* const* d_in, const int* in_sizes, int n_in,
                              void* d_out, int out_size) {
    const float* clf = (const float*)d_in[0];
    const float* reg = (const float*)d_in[1];
    const float* anc = (const float*)d_in[2];
    const float* ann = (const float*)d_in[3];
    float* out = (float*)d_out;

    const int A = in_sizes[2] / 4;                       // anchors: 1*A*4
    const int B = in_sizes[1] / (4 * A);                 // regressions: B*A*4
    const int C = (int)((long long)in_sizes[0] / ((long long)B * A)); // B*A*C
    const int M = in_sizes[3] / (5 * B);                 // annotations: B*M*5

    fl_init_kernel<<<1, 32>>>();

    {   // Phase A: thread per anchor
        const int threads = 256;
        dim3 grid((A + threads - 1) / threads, B);
        fl_match_kernel<<<grid, threads>>>((const float4*)anc, (const float4*)reg,
                                           ann, A, M);
    }

    {   // Phase B: float4 streaming scan
        const int perImgV4 = (A * C) / 4;   // A*C divisible by 4 for this shape
        const int threads = 256;
        int blocksX = (perImgV4 + threads * 8 - 1) / (threads * 8);
        if (blocksX < 1) blocksX = 1;
        dim3 grid(blocksX, B);
        if (C == 90)
            fl_clf_kernel<90><<<grid, threads>>>((const float4*)clf, A, C, perImgV4);
        else
            fl_clf_kernel<0><<<grid, threads>>>((const float4*)clf, A, C, perImgV4);
    }

    fl_fin_kernel<<<1, 32>>>(out, B);
}

// round 3
// speedup vs baseline: 2.3204x; 1.0791x over previous
#include <cuda_runtime.h>
#include <math.h>

// ---------------------------------------------------------------------------
// FocalLoss (RetinaNet-style) on GB300 — two-phase, load-lean streaming.
//   Phase A (match): thread/anchor -> per-anchor weight (0 or 0.75),
//                    reg smooth-L1, matched count, and the pos-branch
//                    correction for the single gt element of matched rows.
//   Phase B (clf):   float4 stream, acc += w[a] * p^2 * (-log(1-p)),
//                    last block finalizes output and resets state.
// Inputs (metadata order):
//   d_in[0] classifications float32 [B, A, C]
//   d_in[1] regressions     float32 [B, A, 4]
//   d_in[2] anchors         float32 [1, A, 4]   (y1, x1, y2, x2)
//   d_in[3] annotations     float32 [B, M, 5]   (x1, y1, x2, y2, label)
// Output: float32 [2] = (clf_loss_weighted, reg_loss_weighted)
// ---------------------------------------------------------------------------

#define FL_EPS    1e-4f
#define FL_ACCEPT 0.5f
#define FL_REJECT 0.4f
#define MAX_B     16
#define MAX_M     128
#define META_CAP  (1 << 20)      // >= B*A (8*49104 = 392832)

__device__ double g_clf_sum[MAX_B];
__device__ double g_sl1_sum[MAX_B];
__device__ int    g_nm[MAX_B];
__device__ float  g_w[META_CAP];     // per (b,a): 0.75 if clf row active, else 0
__device__ unsigned int g_ticket;    // zero-init; self-resetting

// ---------------- Phase A: matching + reg loss + pos correction ------------
__global__ void fl_match_kernel(const float4* __restrict__ anc,
                                const float4* __restrict__ reg,
                                const float* __restrict__ ann,
                                const float* __restrict__ clf,
                                int A, int C, int M) {
    const int b = blockIdx.y;
    const int a = blockIdx.x * blockDim.x + threadIdx.x;

    __shared__ float  s_ann[MAX_M * 5];
    __shared__ double s_sl1, s_cor;
    __shared__ int    s_nm;

    if (threadIdx.x == 0) { s_sl1 = 0.0; s_cor = 0.0; s_nm = 0; }
    const int annN = M * 5;
    for (int i = threadIdx.x; i < annN; i += blockDim.x)
        s_ann[i] = ann[(size_t)b * annN + i];
    __syncthreads();

    if (a < A) {
        const float4 av = anc[a];            // y1, x1, y2, x2
        const float ay1 = av.x, ax1 = av.y, ay2 = av.z, ax2 = av.w;
        const float aarea = (ax2 - ax1) * (ay2 - ay1);

        // sequential argmax keeps jnp.argmax first-index tiebreak
        float v   = -2.0f;
        int   idx = 0;
        for (int j = 0; j < M; j++) {
            const float bx1 = s_ann[j * 5 + 0];
            const float by1 = s_ann[j * 5 + 1];
            const float bx2 = s_ann[j * 5 + 2];
            const float by2 = s_ann[j * 5 + 3];
            float iw = fminf(ax2, bx2) - fmaxf(ax1, bx1); iw = fmaxf(iw, 0.0f);
            float ih = fminf(ay2, by2) - fmaxf(ay1, by1); ih = fmaxf(ih, 0.0f);
            const float inter = iw * ih;
            const float uni = fmaxf(aarea + (bx2 - bx1) * (by2 - by1) - inter, 1e-8f);
            float iou = inter / uni;
            if (s_ann[j * 5 + 4] == -1.0f) iou = -1.0f;
            if (iou > v) { v = iou; idx = j; }
        }

        const bool matched   = v > FL_ACCEPT;
        const bool unmatched = v < FL_REJECT;

        g_w[b * A + a] = (matched || unmatched) ? 0.75f : 0.0f;

        if (matched) {
            // --- pos-branch correction for the gt element -----------------
            const int gt = (int)s_ann[idx * 5 + 4] - 1;
            float p = clf[((size_t)b * A + a) * C + gt];
            p = fminf(fmaxf(p, FL_EPS), 1.0f - FL_EPS);
            const float om = 1.0f - p;
            const float pos = 0.25f * om * om * (-__logf(p));
            const float neg = 0.75f * p * p * (-__logf(om));
            atomicAdd(&s_cor, (double)(pos - neg));

            // --- regression smooth-L1 --------------------------------------
            const float gx1 = s_ann[idx * 5 + 0];
            const float gy1 = s_ann[idx * 5 + 1];
            const float gx2 = s_ann[idx * 5 + 2];
            const float gy2 = s_ann[idx * 5 + 3];
            const float gwr = gx2 - gx1;
            const float ghr = gy2 - gy1;
            const float gcx = gx1 + 0.5f * gwr;
            const float gcy = gy1 + 0.5f * ghr;
            const float gw  = fmaxf(gwr, 1.0f);
            const float gh  = fmaxf(ghr, 1.0f);
            const float aw  = ax2 - ax1;
            const float ah  = ay2 - ay1;
            const float acx = ax1 + 0.5f * aw;
            const float acy = ay1 + 0.5f * ah;
            const float4 rv = reg[(size_t)b * A + a];
            float s = 0.0f;
            {
                float d;
                d = fabsf(9.0f * (rv.x - (gcy - acy) / ah));
                s += (d < 1.0f) ? 0.5f * d * d : (d - 0.5f);
                d = fabsf(9.0f * (rv.y - (gcx - acx) / aw));
                s += (d < 1.0f) ? 0.5f * d * d : (d - 0.5f);
                d = fabsf(9.0f * (rv.z - __logf(gh / ah)));
                s += (d < 1.0f) ? 0.5f * d * d : (d - 0.5f);
                d = fabsf(9.0f * (rv.w - __logf(gw / aw)));
                s += (d < 1.0f) ? 0.5f * d * d : (d - 0.5f);
            }
            atomicAdd(&s_sl1, (double)s);
            atomicAdd(&s_nm, 1);
        }
    }

    __syncthreads();
    if (threadIdx.x == 0) {
        if (s_sl1 != 0.0) atomicAdd(&g_sl1_sum[b], s_sl1);
        if (s_cor != 0.0) atomicAdd(&g_clf_sum[b], s_cor);
        if (s_nm)         atomicAdd(&g_nm[b], s_nm);
    }
}

// ---------------- Phase B: streaming neg-branch focal loss -----------------
__device__ __forceinline__ float fl_neg(float p, float w) {
    p = fminf(fmaxf(p, FL_EPS), 1.0f - FL_EPS);
    return w * p * p * (-__logf(1.0f - p));
}

template <int CC>
__global__ void fl_clf_kernel(const float4* __restrict__ clf,
                              float* __restrict__ out,
                              int A, int C, int B, int perImgV4) {
    const int b  = blockIdx.y;
    const int Cv = (CC > 0) ? CC : C;
    const float4* base = clf + (size_t)b * perImgV4;
    const float* __restrict__ wrow = g_w + b * A;

    float acc = 0.0f;
    const int stride = gridDim.x * blockDim.x;
    for (int i = blockIdx.x * blockDim.x + threadIdx.x; i < perImgV4; i += stride) {
        const float4 v = base[i];
        const int e0 = i * 4;
        const int a0 = e0 / Cv;
        const int c0 = e0 - a0 * Cv;
        const int a3 = (e0 + 3) / Cv;
        const float w0 = __ldg(&wrow[a0]);
        const float w3 = __ldg(&wrow[a3]);
        acc += fl_neg(v.x, w0);
        acc += fl_neg(v.y, (c0 + 1 < Cv) ? w0 : w3);
        acc += fl_neg(v.z, (c0 + 2 < Cv) ? w0 : w3);
        acc += fl_neg(v.w, (c0 + 3 < Cv) ? w0 : w3);
    }

    // tail elements (A*C not multiple of 4), handled once
    if (blockIdx.x == 0 && threadIdx.x == 0) {
        const float* sclf = (const float*)base;
        for (int e = perImgV4 * 4; e < A * Cv; e++) {
            const int a = e / Cv;
            acc += fl_neg(sclf[e], __ldg(&wrow[a]));
        }
    }

    // warp reduce -> shared double -> 1 global atomic per block
    #pragma unroll
    for (int off = 16; off; off >>= 1)
        acc += __shfl_xor_sync(0xffffffffu, acc, off);

    __shared__ double s_acc;
    __shared__ bool   s_last;
    if (threadIdx.x == 0) s_acc = 0.0;
    __syncthreads();
    if ((threadIdx.x & 31) == 0 && acc != 0.0f)
        atomicAdd(&s_acc, (double)acc);
    __syncthreads();
    if (threadIdx.x == 0) {
        if (s_acc != 0.0) atomicAdd(&g_clf_sum[b], s_acc);
        __threadfence();
        const unsigned int total = gridDim.x * gridDim.y;
        const unsigned int t = atomicAdd(&g_ticket, 1u);
        s_last = (t == total - 1u);
    }
    __syncthreads();

    // ---- last block: finalize output + reset state for next replay --------
    if (s_last && threadIdx.x == 0) {
        __threadfence();
        double cl = 0.0, rl = 0.0;
        for (int bb = 0; bb < B; bb++) {
            const int nm = g_nm[bb];
            const int dn = nm > 1 ? nm : 1;
            cl += g_clf_sum[bb] / (double)dn;
            if (nm > 0) rl += g_sl1_sum[bb] / (double)(4 * nm);
            g_clf_sum[bb] = 0.0;
            g_sl1_sum[bb] = 0.0;
            g_nm[bb]      = 0;
        }
        out[0] = (float)(cl / (double)B);          // CLF_W = 1.0
        out[1] = (float)(50.0 * rl / (double)B);   // REG_W = 50.0
        g_ticket = 0u;
    }
}

extern "C" void kernel_launch(void* const* d_in, const int* in_sizes, int n_in,
                              void* d_out, int out_size) {
    const float* clf = (const float*)d_in[0];
    const float* reg = (const float*)d_in[1];
    const float* anc = (const float*)d_in[2];
    const float* ann = (const float*)d_in[3];
    float* out = (float*)d_out;

    const int A = in_sizes[2] / 4;                       // anchors: 1*A*4
    const int B = in_sizes[1] / (4 * A);                 // regressions: B*A*4
    const int C = (int)((long long)in_sizes[0] / ((long long)B * A)); // B*A*C
    const int M = in_sizes[3] / (5 * B);                 // annotations: B*M*5

    {   // Phase A: thread per anchor
        const int threads = 256;
        dim3 grid((A + threads - 1) / threads, B);
        fl_match_kernel<<<grid, threads>>>((const float4*)anc, (const float4*)reg,
                                           ann, clf, A, C, M);
    }

    {   // Phase B: float4 streaming scan + fused finalize
        const int perImgV4 = (A * C) / 4;
        const int threads = 256;
        int blocksX = (perImgV4 + threads * 8 - 1) / (threads * 8);
        if (blocksX < 1) blocksX = 1;
        dim3 grid(blocksX, B);
        if (C == 90)
            fl_clf_kernel<90><<<grid, threads>>>((const float4*)clf, out, A, C, B, perImgV4);
        else
            fl_clf_kernel<0><<<grid, threads>>>((const float4*)clf, out, A, C, B, perImgV4);
    }
}

// round 4
// speedup vs baseline: 2.7187x; 1.1716x over previous
#include <cuda_runtime.h>
#include <math.h>

// ---------------------------------------------------------------------------
// FocalLoss (RetinaNet-style) on GB300 — lean streaming + exact corrections.
//   Phase A (match): thread/anchor. Computes matched/dead status, reg loss,
//                    matched count, the pos-branch correction for gt elems,
//                    and appends dead anchors to a device list.
//   Phase B (clf):   weight-free float4 stream: acc += p'^2 * log2(1-p'),
//                    p' = min(p, 1-eps). After streaming, blocks cancel the
//                    dead rows' contributions (same formula). Last block
//                    finalizes the output and resets all state.
// Inputs (metadata order):
//   d_in[0] classifications float32 [B, A, C]
//   d_in[1] regressions     float32 [B, A, 4]
//   d_in[2] anchors         float32 [1, A, 4]   (y1, x1, y2, x2)
//   d_in[3] annotations     float32 [B, M, 5]   (x1, y1, x2, y2, label)
// Output: float32 [2] = (clf_loss_weighted, reg_loss_weighted)
// ---------------------------------------------------------------------------

#define FL_EPS    1e-4f
#define FL_ACCEPT 0.5f
#define FL_REJECT 0.4f
#define MAX_B     16
#define MAX_M     128
#define META_CAP  (1 << 20)      // >= B*A (8*49104 = 392832)
#define LN2_D     0.693147180559945309

__device__ double g_clf_sum[MAX_B];
__device__ double g_sl1_sum[MAX_B];
__device__ int    g_nm[MAX_B];
__device__ int    g_dead[META_CAP];     // flat (b*A + a) of dead-zone anchors
__device__ unsigned int g_dead_cnt;     // zero-init; reset each replay
__device__ unsigned int g_ticket;       // zero-init; reset each replay

// identical per-element core used by stream AND corrections
__device__ __forceinline__ float fl_core(float p) {
    const float pm = fminf(p, 1.0f - FL_EPS);
    return pm * pm * __log2f(1.0f - pm);      // negative
}

// ---------------- Phase A: matching + reg loss + gt correction -------------
__global__ void fl_match_kernel(const float4* __restrict__ anc,
                                const float4* __restrict__ reg,
                                const float* __restrict__ ann,
                                const float* __restrict__ clf,
                                int A, int C, int M) {
    const int b = blockIdx.y;
    const int a = blockIdx.x * blockDim.x + threadIdx.x;

    __shared__ float  s_ann[MAX_M * 5];
    __shared__ double s_sl1, s_cor;
    __shared__ int    s_nm;

    if (threadIdx.x == 0) { s_sl1 = 0.0; s_cor = 0.0; s_nm = 0; }
    const int annN = M * 5;
    for (int i = threadIdx.x; i < annN; i += blockDim.x)
        s_ann[i] = ann[(size_t)b * annN + i];
    __syncthreads();

    if (a < A) {
        const float4 av = anc[a];            // y1, x1, y2, x2
        const float ay1 = av.x, ax1 = av.y, ay2 = av.z, ax2 = av.w;
        const float aarea = (ax2 - ax1) * (ay2 - ay1);

        // division-free argmax (cross-multiplied compare); keeps first-index
        // tiebreak for the exact-tie case that matters (inter == 0).
        float bestI = 0.0f;     // inter of best
        float bestU = 1.0f;     // union of best  (iou_best = bestI/bestU)
        bool  anyValid = false;
        int   idx = 0;
        for (int j = 0; j < M; j++) {
            if (s_ann[j * 5 + 4] == -1.0f) continue;   // invalid label
            const float bx1 = s_ann[j * 5 + 0];
            const float by1 = s_ann[j * 5 + 1];
            const float bx2 = s_ann[j * 5 + 2];
            const float by2 = s_ann[j * 5 + 3];
            float iw = fminf(ax2, bx2) - fmaxf(ax1, bx1); iw = fmaxf(iw, 0.0f);
            float ih = fminf(ay2, by2) - fmaxf(ay1, by1); ih = fmaxf(ih, 0.0f);
            const float inter = iw * ih;
            const float uni = fmaxf(aarea + (bx2 - bx1) * (by2 - by1) - inter, 1e-8f);
            if (!anyValid) { anyValid = true; bestI = inter; bestU = uni; idx = j; }
            else if (inter * bestU > bestI * uni) { bestI = inter; bestU = uni; idx = j; }
        }
        // NOTE: reference sets iou=-1 for invalid; if no valid boxes, iou_max
        // = -1 -> unmatched (w active) with idx among invalids -> but tgt=0
        // everywhere, handled as plain unmatched row: nothing special needed.
        const float v = anyValid ? (bestI / bestU) : -1.0f;

        const bool matched   = v > FL_ACCEPT;
        const bool unmatched = v < FL_REJECT;

        if (!matched && !unmatched) {
            // dead-zone anchor: enqueue for row cancellation in Phase B
            const unsigned int slot = atomicAdd(&g_dead_cnt, 1u);
            g_dead[slot] = b * A + a;
        }

        if (matched) {
            // --- gt-element correction: replace stream's neg term by pos ---
            const int gt = (int)s_ann[idx * 5 + 4] - 1;
            const float p = clf[((size_t)b * A + a) * C + gt];
            const float pc = fminf(fmaxf(p, FL_EPS), 1.0f - FL_EPS);
            const float om = 1.0f - pc;
            const double pos = (double)(0.25f * om * om * (-__logf(pc)));
            const double st  = (double)fl_core(p) * (-0.75 * LN2_D); // what stream adds
            atomicAdd(&s_cor, pos - st);

            // --- regression smooth-L1 --------------------------------------
            const float gx1 = s_ann[idx * 5 + 0];
            const float gy1 = s_ann[idx * 5 + 1];
            const float gx2 = s_ann[idx * 5 + 2];
            const float gy2 = s_ann[idx * 5 + 3];
            const float gwr = gx2 - gx1;
            const float ghr = gy2 - gy1;
            const float gcx = gx1 + 0.5f * gwr;
            const float gcy = gy1 + 0.5f * ghr;
            const float gw  = fmaxf(gwr, 1.0f);
            const float gh  = fmaxf(ghr, 1.0f);
            const float aw  = ax2 - ax1;
            const float ah  = ay2 - ay1;
            const float acx = ax1 + 0.5f * aw;
            const float acy = ay1 + 0.5f * ah;
            const float4 rv = reg[(size_t)b * A + a];
            float s = 0.0f;
            {
                float d;
                d = fabsf(9.0f * (rv.x - (gcy - acy) / ah));
                s += (d < 1.0f) ? 0.5f * d * d : (d - 0.5f);
                d = fabsf(9.0f * (rv.y - (gcx - acx) / aw));
                s += (d < 1.0f) ? 0.5f * d * d : (d - 0.5f);
                d = fabsf(9.0f * (rv.z - __logf(gh / ah)));
                s += (d < 1.0f) ? 0.5f * d * d : (d - 0.5f);
                d = fabsf(9.0f * (rv.w - __logf(gw / aw)));
                s += (d < 1.0f) ? 0.5f * d * d : (d - 0.5f);
            }
            atomicAdd(&s_sl1, (double)s);
            atomicAdd(&s_nm, 1);
        }
    }

    __syncthreads();
    if (threadIdx.x == 0) {
        if (s_sl1 != 0.0) atomicAdd(&g_sl1_sum[b], s_sl1);
        if (s_cor != 0.0) atomicAdd(&g_clf_sum[b], s_cor);
        if (s_nm)         atomicAdd(&g_nm[b], s_nm);
    }
}

// ---------------- Phase B: weight-free stream + dead-row cancel ------------
__global__ void fl_clf_kernel(const float4* __restrict__ clf4,
                              const float* __restrict__ clf,
                              float* __restrict__ out,
                              int A, int C, int B, int perImgV4) {
    const int b = blockIdx.y;
    const float4* base = clf4 + (size_t)b * perImgV4;

    // ---- main stream: no weights, no index math ---------------------------
    float acc0 = 0.0f, acc1 = 0.0f;
    const int stride = gridDim.x * blockDim.x;
    for (int i = blockIdx.x * blockDim.x + threadIdx.x; i < perImgV4; i += stride) {
        const float4 v = base[i];
        acc0 += fl_core(v.x);
        acc0 += fl_core(v.y);
        acc1 += fl_core(v.z);
        acc1 += fl_core(v.w);
    }
    float acc = acc0 + acc1;
    if (blockIdx.x == 0 && threadIdx.x == 0) {     // scalar tail, if any
        for (int e = perImgV4 * 4; e < A * C; e++)
            acc += fl_core(clf[(size_t)b * A * C + e]);
    }

    #pragma unroll
    for (int off = 16; off; off >>= 1)
        acc += __shfl_xor_sync(0xffffffffu, acc, off);

    __shared__ double s_acc;
    __shared__ double s_corr[MAX_B];
    __shared__ bool   s_last;
    if (threadIdx.x == 0) s_acc = 0.0;
    if (threadIdx.x < MAX_B) s_corr[threadIdx.x] = 0.0;
    __syncthreads();
    if ((threadIdx.x & 31) == 0)
        atomicAdd(&s_acc, (double)acc);

    // ---- dead-row cancellation (same formula => exact cancel) -------------
    {
        const unsigned int cnt = g_dead_cnt;       // written before this launch
        if (cnt) {
            const int lane   = threadIdx.x & 31;
            const int warpId = threadIdx.x >> 5;
            const int wpb    = blockDim.x >> 5;
            const unsigned int flat  = blockIdx.y * gridDim.x + blockIdx.x;
            const unsigned int nflat = gridDim.x * gridDim.y;
            for (unsigned int r = flat * wpb + warpId; r < cnt; r += nflat * wpb) {
                const int key = g_dead[r];
                const int bb  = key / A;
                const float* row = clf + (size_t)key * C;
                float s = 0.0f;
                for (int c = lane; c < C; c += 32)
                    s += fl_core(row[c]);
                #pragma unroll
                for (int off = 16; off; off >>= 1)
                    s += __shfl_xor_sync(0xffffffffu, s, off);
                if (lane == 0)
                    atomicAdd(&s_corr[bb], (double)s * (0.75 * LN2_D));
            }
        }
    }
    __syncthreads();

    if (threadIdx.x == 0) {
        // stream contribution: (-0.75*ln2) * raw_log2_sum  (positive)
        atomicAdd(&g_clf_sum[b], s_acc * (-0.75 * LN2_D));
        for (int bb = 0; bb < B; bb++)
            if (s_corr[bb] != 0.0) atomicAdd(&g_clf_sum[bb], s_corr[bb]);
        __threadfence();
        const unsigned int total = gridDim.x * gridDim.y;
        const unsigned int t = atomicAdd(&g_ticket, 1u);
        s_last = (t == total - 1u);
    }
    __syncthreads();

    // ---- last block: finalize output + reset state for next replay --------
    if (s_last && threadIdx.x == 0) {
        __threadfence();
        double cl = 0.0, rl = 0.0;
        for (int bb = 0; bb < B; bb++) {
            const int nm = g_nm[bb];
            const int dn = nm > 1 ? nm : 1;
            cl += g_clf_sum[bb] / (double)dn;
            if (nm > 0) rl += g_sl1_sum[bb] / (double)(4 * nm);
            g_clf_sum[bb] = 0.0;
            g_sl1_sum[bb] = 0.0;
            g_nm[bb]      = 0;
        }
        out[0] = (float)(cl / (double)B);          // CLF_W = 1.0
        out[1] = (float)(50.0 * rl / (double)B);   // REG_W = 50.0
        g_dead_cnt = 0u;
        g_ticket   = 0u;
    }
}

extern "C" void kernel_launch(void* const* d_in, const int* in_sizes, int n_in,
                              void* d_out, int out_size) {
    const float* clf = (const float*)d_in[0];
    const float* reg = (const float*)d_in[1];
    const float* anc = (const float*)d_in[2];
    const float* ann = (const float*)d_in[3];
    float* out = (float*)d_out;

    const int A = in_sizes[2] / 4;                       // anchors: 1*A*4
    const int B = in_sizes[1] / (4 * A);                 // regressions: B*A*4
    const int C = (int)((long long)in_sizes[0] / ((long long)B * A)); // B*A*C
    const int M = in_sizes[3] / (5 * B);                 // annotations: B*M*5

    {   // Phase A: thread per anchor
        const int threads = 256;
        dim3 grid((A + threads - 1) / threads, B);
        fl_match_kernel<<<grid, threads>>>((const float4*)anc, (const float4*)reg,
                                           ann, clf, A, C, M);
    }

    {   // Phase B: float4 streaming scan + corrections + fused finalize
        const int perImgV4 = (A * C) / 4;
        const int threads = 256;
        int blocksX = (perImgV4 + threads * 8 - 1) / (threads * 8);
        if (blocksX < 1) blocksX = 1;
        dim3 grid(blocksX, B);
        fl_clf_kernel<<<grid, threads>>>((const float4*)clf, clf, out,
                                         A, C, B, perImgV4);
    }
}

// round 5
// speedup vs baseline: 2.9548x; 1.0868x over previous
#include <cuda_runtime.h>
#include <math.h>

// ---------------------------------------------------------------------------
// FocalLoss (RetinaNet-style) on GB300 — single fused kernel.
//  - Blocks whose x-range covers anchors do per-anchor matching first:
//      * matched: reg smooth-L1, count, gt-element pos-correction
//      * dead-zone: cancel own clf row's stream contribution (exact formula)
//  - All blocks then stream the clf tensor (weight-free, MLP=4 float4 loads):
//      acc += p'^2 * log2(1-p'),  scaled once by -0.75*ln2.
//  - Ticket: last block finalizes the two outputs and resets state.
// Inputs (metadata order):
//   d_in[0] classifications float32 [B, A, C]
//   d_in[1] regressions     float32 [B, A, 4]
//   d_in[2] anchors         float32 [1, A, 4]   (y1, x1, y2, x2)
//   d_in[3] annotations     float32 [B, M, 5]   (x1, y1, x2, y2, label)
// Output: float32 [2] = (clf_loss_weighted, reg_loss_weighted)
// ---------------------------------------------------------------------------

#define FL_EPS    1e-4f
#define MAX_B     16
#define MAX_M     128
#define LN2_D     0.693147180559945309

__device__ double g_clf_sum[MAX_B];
__device__ double g_sl1_sum[MAX_B];
__device__ int    g_nm[MAX_B];
__device__ unsigned int g_ticket;    // zero-init; self-resetting each replay

// identical per-element core used by stream AND all corrections
__device__ __forceinline__ float fl_core(float p) {
    const float pm = fminf(p, 1.0f - FL_EPS);
    return pm * pm * __log2f(1.0f - pm);      // negative
}

__global__ __launch_bounds__(256, 4)
void fl_fused_kernel(const float4* __restrict__ clf4,
                     const float*  __restrict__ clf,
                     const float4* __restrict__ reg,
                     const float4* __restrict__ anc,
                     const float*  __restrict__ ann,
                     float* __restrict__ out,
                     int A, int C, int B, int M, int perImgV4) {
    const int b = blockIdx.y;
    const int a = blockIdx.x * blockDim.x + threadIdx.x;

    __shared__ float  s_raw[MAX_M * 5];
    __shared__ float  s_bx1[MAX_M], s_by1[MAX_M], s_bx2[MAX_M], s_by2[MAX_M];
    __shared__ float  s_bar[MAX_M], s_lbl[MAX_M];
    __shared__ int    s_nv;
    __shared__ double s_sl1, s_cor, s_acc;
    __shared__ int    s_nm;
    __shared__ bool   s_last;

    const bool blockHasAnchors = (blockIdx.x * blockDim.x) < A;

    if (threadIdx.x == 0) { s_sl1 = 0.0; s_cor = 0.0; s_acc = 0.0; s_nm = 0; }
    if (blockHasAnchors) {
        const int annN = M * 5;
        for (int i = threadIdx.x; i < annN; i += blockDim.x)
            s_raw[i] = ann[(size_t)b * annN + i];
    }
    __syncthreads();
    if (blockHasAnchors && threadIdx.x == 0) {
        int nv = 0;
        for (int j = 0; j < M; j++) {
            const float lbl = s_raw[j * 5 + 4];
            if (lbl == -1.0f) continue;             // order preserved -> tiebreak ok
            const float bx1 = s_raw[j * 5 + 0];
            const float by1 = s_raw[j * 5 + 1];
            const float bx2 = s_raw[j * 5 + 2];
            const float by2 = s_raw[j * 5 + 3];
            s_bx1[nv] = bx1; s_by1[nv] = by1;
            s_bx2[nv] = bx2; s_by2[nv] = by2;
            s_bar[nv] = (bx2 - bx1) * (by2 - by1);
            s_lbl[nv] = lbl;
            nv++;
        }
        s_nv = nv;
    }
    __syncthreads();

    // ======================= Part 1: matching ==============================
    if (blockHasAnchors && a < A) {
        const float4 av = anc[a];            // y1, x1, y2, x2
        const float ay1 = av.x, ax1 = av.y, ay2 = av.z, ax2 = av.w;
        const float aarea = (ax2 - ax1) * (ay2 - ay1);
        const int nv = s_nv;

        // division-free argmax over valid boxes (first-index tiebreak kept)
        float bestI = 0.0f, bestU = 1.0f;
        int   idx = -1;
        for (int j = 0; j < nv; j++) {
            float iw = fminf(ax2, s_bx2[j]) - fmaxf(ax1, s_bx1[j]); iw = fmaxf(iw, 0.0f);
            float ih = fminf(ay2, s_by2[j]) - fmaxf(ay1, s_by1[j]); ih = fmaxf(ih, 0.0f);
            const float inter = iw * ih;
            const float uni = fmaxf(aarea + s_bar[j] - inter, 1e-8f);
            if (idx < 0) { bestI = inter; bestU = uni; idx = j; }
            else if (inter * bestU > bestI * uni) { bestI = inter; bestU = uni; idx = j; }
        }
        const float v = (idx >= 0) ? (bestI / bestU) : -1.0f;
        const bool matched   = v > 0.5f;
        const bool unmatched = v < 0.4f;

        if (!matched && !unmatched) {
            // dead-zone: cancel this row's stream contribution (exact formula)
            const float* row = clf + ((size_t)b * A + a) * C;
            float s = 0.0f;
            for (int c = 0; c < C; c++) s += fl_core(row[c]);
            atomicAdd(&s_cor, (double)s * (0.75 * LN2_D));
        } else if (matched) {
            // gt-element correction: replace stream's neg term with pos term
            const int gt = (int)s_lbl[idx] - 1;
            const float p = clf[((size_t)b * A + a) * C + gt];
            const float pc = fminf(fmaxf(p, FL_EPS), 1.0f - FL_EPS);
            const float om = 1.0f - pc;
            const double pos = (double)(0.25f * om * om * (-__logf(pc)));
            const double st  = (double)fl_core(p) * (-0.75 * LN2_D);
            atomicAdd(&s_cor, pos - st);

            // regression smooth-L1
            const float gx1 = s_bx1[idx], gy1 = s_by1[idx];
            const float gx2 = s_bx2[idx], gy2 = s_by2[idx];
            const float gwr = gx2 - gx1, ghr = gy2 - gy1;
            const float gcx = gx1 + 0.5f * gwr, gcy = gy1 + 0.5f * ghr;
            const float gw = fmaxf(gwr, 1.0f),  gh = fmaxf(ghr, 1.0f);
            const float aw = ax2 - ax1, ah = ay2 - ay1;
            const float acx = ax1 + 0.5f * aw, acy = ay1 + 0.5f * ah;
            const float4 rv = reg[(size_t)b * A + a];
            float s = 0.0f;
            float d;
            d = fabsf(9.0f * (rv.x - (gcy - acy) / ah));
            s += (d < 1.0f) ? 0.5f * d * d : (d - 0.5f);
            d = fabsf(9.0f * (rv.y - (gcx - acx) / aw));
            s += (d < 1.0f) ? 0.5f * d * d : (d - 0.5f);
            d = fabsf(9.0f * (rv.z - __logf(gh / ah)));
            s += (d < 1.0f) ? 0.5f * d * d : (d - 0.5f);
            d = fabsf(9.0f * (rv.w - __logf(gw / aw)));
            s += (d < 1.0f) ? 0.5f * d * d : (d - 0.5f);
            atomicAdd(&s_sl1, (double)s);
            atomicAdd(&s_nm, 1);
        }
    }

    // ======================= Part 2: stream (MLP = 4) ======================
    {
        const float4* base = clf4 + (size_t)b * perImgV4;
        float acc0 = 0.0f, acc1 = 0.0f;
        const int stride = gridDim.x * blockDim.x;
        int i = blockIdx.x * blockDim.x + threadIdx.x;
        for (; i + 3 * stride < perImgV4; i += 4 * stride) {
            const float4 v0 = base[i];
            const float4 v1 = base[i + stride];
            const float4 v2 = base[i + 2 * stride];
            const float4 v3 = base[i + 3 * stride];
            acc0 += fl_core(v0.x) + fl_core(v0.y);
            acc1 += fl_core(v0.z) + fl_core(v0.w);
            acc0 += fl_core(v1.x) + fl_core(v1.y);
            acc1 += fl_core(v1.z) + fl_core(v1.w);
            acc0 += fl_core(v2.x) + fl_core(v2.y);
            acc1 += fl_core(v2.z) + fl_core(v2.w);
            acc0 += fl_core(v3.x) + fl_core(v3.y);
            acc1 += fl_core(v3.z) + fl_core(v3.w);
        }
        for (; i < perImgV4; i += stride) {
            const float4 v = base[i];
            acc0 += fl_core(v.x) + fl_core(v.y);
            acc1 += fl_core(v.z) + fl_core(v.w);
        }
        float acc = acc0 + acc1;
        if (blockIdx.x == 0 && threadIdx.x == 0) {     // scalar tail, if any
            for (int e = perImgV4 * 4; e < A * C; e++)
                acc += fl_core(clf[(size_t)b * A * C + e]);
        }
        #pragma unroll
        for (int off = 16; off; off >>= 1)
            acc += __shfl_xor_sync(0xffffffffu, acc, off);
        if ((threadIdx.x & 31) == 0)
            atomicAdd(&s_acc, (double)acc);
    }
    __syncthreads();

    // ======================= Part 3: accumulate + finalize =================
    if (threadIdx.x == 0) {
        const double clfAdd = s_acc * (-0.75 * LN2_D) + s_cor;
        if (clfAdd != 0.0) atomicAdd(&g_clf_sum[b], clfAdd);
        if (s_sl1 != 0.0)  atomicAdd(&g_sl1_sum[b], s_sl1);
        if (s_nm)          atomicAdd(&g_nm[b], s_nm);
        __threadfence();
        const unsigned int total = gridDim.x * gridDim.y;
        const unsigned int t = atomicAdd(&g_ticket, 1u);
        s_last = (t == total - 1u);
    }
    __syncthreads();

    if (s_last && threadIdx.x == 0) {
        __threadfence();
        double cl = 0.0, rl = 0.0;
        for (int bb = 0; bb < B; bb++) {
            const int nm = g_nm[bb];
            const int dn = nm > 1 ? nm : 1;
            cl += g_clf_sum[bb] / (double)dn;
            if (nm > 0) rl += g_sl1_sum[bb] / (double)(4 * nm);
            g_clf_sum[bb] = 0.0;
            g_sl1_sum[bb] = 0.0;
            g_nm[bb]      = 0;
        }
        out[0] = (float)(cl / (double)B);          // CLF_W = 1.0
        out[1] = (float)(50.0 * rl / (double)B);   // REG_W = 50.0
        g_ticket = 0u;
    }
}

extern "C" void kernel_launch(void* const* d_in, const int* in_sizes, int n_in,
                              void* d_out, int out_size) {
    const float* clf = (const float*)d_in[0];
    const float* reg = (const float*)d_in[1];
    const float* anc = (const float*)d_in[2];
    const float* ann = (const float*)d_in[3];
    float* out = (float*)d_out;

    const int A = in_sizes[2] / 4;                       // anchors: 1*A*4
    const int B = in_sizes[1] / (4 * A);                 // regressions: B*A*4
    const int C = (int)((long long)in_sizes[0] / ((long long)B * A)); // B*A*C
    const int M = in_sizes[3] / (5 * B);                 // annotations: B*M*5

    const int threads  = 256;
    const int perImgV4 = (A * C) / 4;
    int blocksX = (perImgV4 + threads * 8 - 1) / (threads * 8);
    const int needX = (A + threads - 1) / threads;       // cover all anchors
    if (blocksX < needX) blocksX = needX;
    if (blocksX < 1) blocksX = 1;
    dim3 grid(blocksX, B);
    fl_fused_kernel<<<grid, threads>>>((const float4*)clf, clf,
                                       (const float4*)reg, (const float4*)anc,
                                       ann, out, A, C, B, M, perImgV4);
}

// round 6
// speedup vs baseline: 3.4064x; 1.1528x over previous
#include <cuda_runtime.h>
#include <math.h>

// ---------------------------------------------------------------------------
// FocalLoss (RetinaNet-style) on GB300 — single fused kernel, tile streaming.
//  - First blocks per image do per-anchor matching:
//      * matched: reg smooth-L1, count, gt-element pos-correction
//      * dead-zone: cancel own clf row's stream contribution (exact formula)
//  - All blocks stream the clf tensor over CONTIGUOUS 64KB tiles
//      (256 thr x 16 float4, 4-way load batching 4KB apart -> page-local):
//      acc += p'^2 * log2(1-p'),  scaled once by -0.75*ln2.
//  - Ticket: last block finalizes the two outputs and resets state.
// Inputs (metadata order):
//   d_in[0] classifications float32 [B, A, C]
//   d_in[1] regressions     float32 [B, A, 4]
//   d_in[2] anchors         float32 [1, A, 4]   (y1, x1, y2, x2)
//   d_in[3] annotations     float32 [B, M, 5]   (x1, y1, x2, y2, label)
// Output: float32 [2] = (clf_loss_weighted, reg_loss_weighted)
// ---------------------------------------------------------------------------

#define FL_EPS    1e-4f
#define MAX_B     16
#define MAX_M     128
#define LN2_D     0.693147180559945309
#define TILE_K    16                      // float4 per thread per tile
#define THREADS   256
#define TILE_V4   (THREADS * TILE_K)      // 4096 float4 = 64KB

__device__ double g_clf_sum[MAX_B];
__device__ double g_sl1_sum[MAX_B];
__device__ int    g_nm[MAX_B];
__device__ unsigned int g_ticket;    // zero-init; self-resetting each replay

// identical per-element core used by stream AND all corrections
__device__ __forceinline__ float fl_core(float p) {
    const float pm = fminf(p, 1.0f - FL_EPS);
    return pm * pm * __log2f(1.0f - pm);      // negative
}

__global__ __launch_bounds__(THREADS, 8)
void fl_fused_kernel(const float4* __restrict__ clf4,
                     const float*  __restrict__ clf,
                     const float4* __restrict__ reg,
                     const float4* __restrict__ anc,
                     const float*  __restrict__ ann,
                     float* __restrict__ out,
                     int A, int C, int B, int M, int perImgV4) {
    const int b = blockIdx.y;
    const int a = blockIdx.x * blockDim.x + threadIdx.x;

    __shared__ float  s_raw[MAX_M * 5];
    __shared__ float  s_bx1[MAX_M], s_by1[MAX_M], s_bx2[MAX_M], s_by2[MAX_M];
    __shared__ float  s_bar[MAX_M], s_lbl[MAX_M];
    __shared__ int    s_nv;
    __shared__ double s_sl1, s_cor, s_acc;
    __shared__ int    s_nm;
    __shared__ bool   s_last;

    const bool blockHasAnchors = (blockIdx.x * blockDim.x) < A;

    if (threadIdx.x == 0) { s_sl1 = 0.0; s_cor = 0.0; s_acc = 0.0; s_nm = 0; }
    if (blockHasAnchors) {
        const int annN = M * 5;
        for (int i = threadIdx.x; i < annN; i += blockDim.x)
            s_raw[i] = ann[(size_t)b * annN + i];
    }
    __syncthreads();
    if (blockHasAnchors && threadIdx.x == 0) {
        int nv = 0;
        for (int j = 0; j < M; j++) {
            const float lbl = s_raw[j * 5 + 4];
            if (lbl == -1.0f) continue;             // order preserved -> tiebreak ok
            const float bx1 = s_raw[j * 5 + 0];
            const float by1 = s_raw[j * 5 + 1];
            const float bx2 = s_raw[j * 5 + 2];
            const float by2 = s_raw[j * 5 + 3];
            s_bx1[nv] = bx1; s_by1[nv] = by1;
            s_bx2[nv] = bx2; s_by2[nv] = by2;
            s_bar[nv] = (bx2 - bx1) * (by2 - by1);
            s_lbl[nv] = lbl;
            nv++;
        }
        s_nv = nv;
    }
    __syncthreads();

    // ======================= Part 1: matching ==============================
    if (blockHasAnchors && a < A) {
        const float4 av = anc[a];            // y1, x1, y2, x2
        const float ay1 = av.x, ax1 = av.y, ay2 = av.z, ax2 = av.w;
        const float aarea = (ax2 - ax1) * (ay2 - ay1);
        const int nv = s_nv;

        // division-free argmax over valid boxes (first-index tiebreak kept)
        float bestI = 0.0f, bestU = 1.0f;
        int   idx = -1;
        for (int j = 0; j < nv; j++) {
            float iw = fminf(ax2, s_bx2[j]) - fmaxf(ax1, s_bx1[j]); iw = fmaxf(iw, 0.0f);
            float ih = fminf(ay2, s_by2[j]) - fmaxf(ay1, s_by1[j]); ih = fmaxf(ih, 0.0f);
            const float inter = iw * ih;
            const float uni = fmaxf(aarea + s_bar[j] - inter, 1e-8f);
            if (idx < 0) { bestI = inter; bestU = uni; idx = j; }
            else if (inter * bestU > bestI * uni) { bestI = inter; bestU = uni; idx = j; }
        }
        const float v = (idx >= 0) ? (bestI / bestU) : -1.0f;
        const bool matched   = v > 0.5f;
        const bool unmatched = v < 0.4f;

        if (!matched && !unmatched) {
            // dead-zone: cancel this row's stream contribution (exact formula)
            const float* row = clf + ((size_t)b * A + a) * C;
            float s = 0.0f;
            for (int c = 0; c < C; c++) s += fl_core(row[c]);
            atomicAdd(&s_cor, (double)s * (0.75 * LN2_D));
        } else if (matched) {
            // gt-element correction: replace stream's neg term with pos term
            const int gt = (int)s_lbl[idx] - 1;
            const float p = clf[((size_t)b * A + a) * C + gt];
            const float pc = fminf(fmaxf(p, FL_EPS), 1.0f - FL_EPS);
            const float om = 1.0f - pc;
            const double pos = (double)(0.25f * om * om * (-__logf(pc)));
            const double st  = (double)fl_core(p) * (-0.75 * LN2_D);
            atomicAdd(&s_cor, pos - st);

            // regression smooth-L1
            const float gx1 = s_bx1[idx], gy1 = s_by1[idx];
            const float gx2 = s_bx2[idx], gy2 = s_by2[idx];
            const float gwr = gx2 - gx1, ghr = gy2 - gy1;
            const float gcx = gx1 + 0.5f * gwr, gcy = gy1 + 0.5f * ghr;
            const float gw = fmaxf(gwr, 1.0f),  gh = fmaxf(ghr, 1.0f);
            const float aw = ax2 - ax1, ah = ay2 - ay1;
            const float acx = ax1 + 0.5f * aw, acy = ay1 + 0.5f * ah;
            const float4 rv = reg[(size_t)b * A + a];
            float s = 0.0f;
            float d;
            d = fabsf(9.0f * (rv.x - (gcy - acy) / ah));
            s += (d < 1.0f) ? 0.5f * d * d : (d - 0.5f);
            d = fabsf(9.0f * (rv.y - (gcx - acx) / aw));
            s += (d < 1.0f) ? 0.5f * d * d : (d - 0.5f);
            d = fabsf(9.0f * (rv.z - __logf(gh / ah)));
            s += (d < 1.0f) ? 0.5f * d * d : (d - 0.5f);
            d = fabsf(9.0f * (rv.w - __logf(gw / aw)));
            s += (d < 1.0f) ? 0.5f * d * d : (d - 0.5f);
            atomicAdd(&s_sl1, (double)s);
            atomicAdd(&s_nm, 1);
        }
    }

    // ================= Part 2: contiguous-tile stream ======================
    {
        const float4* base = clf4 + (size_t)b * perImgV4;
        const int ntiles = (perImgV4 + TILE_V4 - 1) / TILE_V4;
        float acc0 = 0.0f, acc1 = 0.0f;
        for (int t = blockIdx.x; t < ntiles; t += gridDim.x) {
            const int i0 = t * TILE_V4 + threadIdx.x;
            if (t * TILE_V4 + TILE_V4 <= perImgV4) {
                // full tile: unguarded, 4-way batched loads 4KB apart
                #pragma unroll
                for (int k = 0; k < TILE_K; k += 4) {
                    const float4 v0 = base[i0 + (k + 0) * THREADS];
                    const float4 v1 = base[i0 + (k + 1) * THREADS];
                    const float4 v2 = base[i0 + (k + 2) * THREADS];
                    const float4 v3 = base[i0 + (k + 3) * THREADS];
                    acc0 += fl_core(v0.x) + fl_core(v0.y);
                    acc1 += fl_core(v0.z) + fl_core(v0.w);
                    acc0 += fl_core(v1.x) + fl_core(v1.y);
                    acc1 += fl_core(v1.z) + fl_core(v1.w);
                    acc0 += fl_core(v2.x) + fl_core(v2.y);
                    acc1 += fl_core(v2.z) + fl_core(v2.w);
                    acc0 += fl_core(v3.x) + fl_core(v3.y);
                    acc1 += fl_core(v3.z) + fl_core(v3.w);
                }
            } else {
                for (int k = 0; k < TILE_K; k++) {
                    const int ii = i0 + k * THREADS;
                    if (ii < perImgV4) {
                        const float4 v = base[ii];
                        acc0 += fl_core(v.x) + fl_core(v.y);
                        acc1 += fl_core(v.z) + fl_core(v.w);
                    }
                }
            }
        }
        float acc = acc0 + acc1;
        if (blockIdx.x == 0 && threadIdx.x == 0) {     // scalar tail, if any
            for (int e = perImgV4 * 4; e < A * C; e++)
                acc += fl_core(clf[(size_t)b * A * C + e]);
        }
        #pragma unroll
        for (int off = 16; off; off >>= 1)
            acc += __shfl_xor_sync(0xffffffffu, acc, off);
        if ((threadIdx.x & 31) == 0)
            atomicAdd(&s_acc, (double)acc);
    }
    __syncthreads();

    // ======================= Part 3: accumulate + finalize =================
    if (threadIdx.x == 0) {
        const double clfAdd = s_acc * (-0.75 * LN2_D) + s_cor;
        if (clfAdd != 0.0) atomicAdd(&g_clf_sum[b], clfAdd);
        if (s_sl1 != 0.0)  atomicAdd(&g_sl1_sum[b], s_sl1);
        if (s_nm)          atomicAdd(&g_nm[b], s_nm);
        __threadfence();
        const unsigned int total = gridDim.x * gridDim.y;
        const unsigned int t = atomicAdd(&g_ticket, 1u);
        s_last = (t == total - 1u);
    }
    __syncthreads();

    if (s_last && threadIdx.x == 0) {
        __threadfence();
        double cl = 0.0, rl = 0.0;
        for (int bb = 0; bb < B; bb++) {
            const int nm = g_nm[bb];
            const int dn = nm > 1 ? nm : 1;
            cl += g_clf_sum[bb] / (double)dn;
            if (nm > 0) rl += g_sl1_sum[bb] / (double)(4 * nm);
            g_clf_sum[bb] = 0.0;
            g_sl1_sum[bb] = 0.0;
            g_nm[bb]      = 0;
        }
        out[0] = (float)(cl / (double)B);          // CLF_W = 1.0
        out[1] = (float)(50.0 * rl / (double)B);   // REG_W = 50.0
        g_ticket = 0u;
    }
}

extern "C" void kernel_launch(void* const* d_in, const int* in_sizes, int n_in,
                              void* d_out, int out_size) {
    const float* clf = (const float*)d_in[0];
    const float* reg = (const float*)d_in[1];
    const float* anc = (const float*)d_in[2];
    const float* ann = (const float*)d_in[3];
    float* out = (float*)d_out;

    const int A = in_sizes[2] / 4;                       // anchors: 1*A*4
    const int B = in_sizes[1] / (4 * A);                 // regressions: B*A*4
    const int C = (int)((long long)in_sizes[0] / ((long long)B * A)); // B*A*C
    const int M = in_sizes[3] / (5 * B);                 // annotations: B*M*5

    const int perImgV4 = (A * C) / 4;
    const int ntiles = (perImgV4 + TILE_V4 - 1) / TILE_V4;
    const int needX  = (A + THREADS - 1) / THREADS;      // cover all anchors
    int blocksX = ntiles;                                 // one tile per block pass
    if (blocksX < needX) blocksX = needX;
    if (blocksX < 1) blocksX = 1;
    dim3 grid(blocksX, B);
    fl_fused_kernel<<<grid, THREADS>>>((const float4*)clf, clf,
                                       (const float4*)reg, (const float4*)anc,
                                       ann, out, A, C, B, M, perImgV4);
}